// round 2
// baseline (speedup 1.0000x reference)
#include <cuda_runtime.h>
#include <cuda_bf16.h>
#include <cstdint>

#define N_NODES 100000
#define IN_F    256
#define OUT_F   128
#define NEG_SLOPE 0.2f

// Scratch for support = LeakyReLU(features @ W^T): 100000 x 128 fp32 = 51.2 MB
__device__ float g_support[(size_t)N_NODES * OUT_F];

// ---------------------------------------------------------------------------
// Kernel 1: zero the output (poisoned to 0xAA by harness)
// ---------------------------------------------------------------------------
__global__ void zero_out_kernel(float4* __restrict__ out, int n4) {
    int i = blockIdx.x * blockDim.x + threadIdx.x;
    if (i < n4) out[i] = make_float4(0.f, 0.f, 0.f, 0.f);
}

// ---------------------------------------------------------------------------
// Kernel 2: SGEMM (fp32) + LeakyReLU -> g_support
//   support[n][o] = lrelu( sum_k features[n][k] * weight[o][k] )
//   BM=128, BN=128 (=OUT_F), BK=16, TM=TN=8, 256 threads
// ---------------------------------------------------------------------------
constexpr int BM = 128, BN = 128, BK = 16, TM = 8, TN = 8;

__global__ void __launch_bounds__(256, 2)
gemm_lrelu_kernel(const float* __restrict__ A,   // [N_NODES, IN_F]
                  const float* __restrict__ W,   // [OUT_F, IN_F]
                  float* __restrict__ S)         // [N_NODES, OUT_F]
{
    __shared__ float As[BK][BM];
    __shared__ float Bs[BK][BN];

    const int tid  = threadIdx.x;
    const int rowBase = blockIdx.x * BM;

    const int tRow = tid / (BN / TN);   // 0..15
    const int tCol = tid % (BN / TN);   // 0..15

    // Loader mapping: each thread loads 2 float4 per tile (A and B each).
    const int ldRow  = tid >> 2;        // 0..63
    const int ldCol4 = tid & 3;         // float4 index within 16-float k-chunk

    float acc[TM][TN];
    #pragma unroll
    for (int i = 0; i < TM; i++)
        #pragma unroll
        for (int j = 0; j < TN; j++) acc[i][j] = 0.f;

    for (int kt = 0; kt < IN_F; kt += BK) {
        // Load A tile (features), transposed into As[k][m]
        #pragma unroll
        for (int r = 0; r < 2; r++) {
            int m    = ldRow + r * 64;
            int grow = rowBase + m;
            float4 v = make_float4(0.f, 0.f, 0.f, 0.f);
            if (grow < N_NODES)
                v = *(const float4*)(A + (size_t)grow * IN_F + kt + ldCol4 * 4);
            As[ldCol4 * 4 + 0][m] = v.x;
            As[ldCol4 * 4 + 1][m] = v.y;
            As[ldCol4 * 4 + 2][m] = v.z;
            As[ldCol4 * 4 + 3][m] = v.w;
        }
        // Load B tile (weight rows o = output features), transposed into Bs[k][o]
        #pragma unroll
        for (int r = 0; r < 2; r++) {
            int o = ldRow + r * 64;     // OUT_F = 128, always in range
            float4 v = *(const float4*)(W + (size_t)o * IN_F + kt + ldCol4 * 4);
            Bs[ldCol4 * 4 + 0][o] = v.x;
            Bs[ldCol4 * 4 + 1][o] = v.y;
            Bs[ldCol4 * 4 + 2][o] = v.z;
            Bs[ldCol4 * 4 + 3][o] = v.w;
        }
        __syncthreads();

        #pragma unroll
        for (int k = 0; k < BK; k++) {
            float rm[TM], rn[TN];
            #pragma unroll
            for (int i = 0; i < TM; i++) rm[i] = As[k][tRow * TM + i];
            #pragma unroll
            for (int j = 0; j < TN; j++) rn[j] = Bs[k][tCol * TN + j];
            #pragma unroll
            for (int i = 0; i < TM; i++)
                #pragma unroll
                for (int j = 0; j < TN; j++)
                    acc[i][j] = fmaf(rm[i], rn[j], acc[i][j]);
        }
        __syncthreads();
    }

    // Epilogue: LeakyReLU + store
    #pragma unroll
    for (int i = 0; i < TM; i++) {
        int row = rowBase + tRow * TM + i;
        if (row >= N_NODES) continue;
        #pragma unroll
        for (int j4 = 0; j4 < TN / 4; j4++) {
            float4 v;
            float a0 = acc[i][j4 * 4 + 0];
            float a1 = acc[i][j4 * 4 + 1];
            float a2 = acc[i][j4 * 4 + 2];
            float a3 = acc[i][j4 * 4 + 3];
            v.x = a0 > 0.f ? a0 : NEG_SLOPE * a0;
            v.y = a1 > 0.f ? a1 : NEG_SLOPE * a1;
            v.z = a2 > 0.f ? a2 : NEG_SLOPE * a2;
            v.w = a3 > 0.f ? a3 : NEG_SLOPE * a3;
            *(float4*)(S + (size_t)row * OUT_F + tCol * TN + j4 * 4) = v;
        }
    }
}

// ---------------------------------------------------------------------------
// Kernel 3: SpMM scatter — warp per edge, float4 lanes, vector reduction
//   out[r] += v * support[c]
// ---------------------------------------------------------------------------
__global__ void __launch_bounds__(256)
spmm_kernel(const float* __restrict__ S,
            const float* __restrict__ edge_vals,
            const int*   __restrict__ edge_rows,
            const int*   __restrict__ edge_cols,
            float* __restrict__ out,
            int n_edges)
{
    int e    = (blockIdx.x * blockDim.x + threadIdx.x) >> 5;
    int lane = threadIdx.x & 31;
    if (e >= n_edges) return;

    int   r = edge_rows[e];
    int   c = edge_cols[e];
    float v = edge_vals[e];

    float4 g = ((const float4*)(S + (size_t)c * OUT_F))[lane];
    float4* dst = ((float4*)(out + (size_t)r * OUT_F)) + lane;

    asm volatile("red.global.add.v4.f32 [%0], {%1, %2, %3, %4};"
                 :: "l"(dst), "f"(g.x * v), "f"(g.y * v), "f"(g.z * v), "f"(g.w * v)
                 : "memory");
}

// ---------------------------------------------------------------------------
// Launch
// ---------------------------------------------------------------------------
extern "C" void kernel_launch(void* const* d_in, const int* in_sizes, int n_in,
                              void* d_out, int out_size)
{
    const float* features  = (const float*)d_in[0];
    const float* weight    = (const float*)d_in[1];
    const float* edge_vals = (const float*)d_in[2];
    const int*   edge_rows = (const int*)d_in[3];
    const int*   edge_cols = (const int*)d_in[4];
    float* out = (float*)d_out;

    const int n_edges = in_sizes[2];

    float* support;
    cudaGetSymbolAddress((void**)&support, g_support);

    // 1) zero output
    {
        int n4 = out_size / 4;
        int threads = 256;
        int blocks = (n4 + threads - 1) / threads;
        zero_out_kernel<<<blocks, threads>>>((float4*)out, n4);
    }

    // 2) GEMM + LeakyReLU
    {
        int blocks = (N_NODES + BM - 1) / BM;   // 782
        gemm_lrelu_kernel<<<blocks, 256>>>(features, weight, support);
    }

    // 3) SpMM scatter
    {
        int warps_per_block = 256 / 32;         // 8 edges per block
        int blocks = (n_edges + warps_per_block - 1) / warps_per_block;
        spmm_kernel<<<blocks, 256>>>(support, edge_vals, edge_rows, edge_cols,
                                     out, n_edges);
    }
}

// round 4
// speedup vs baseline: 1.2655x; 1.2655x over previous
#include <cuda_runtime.h>
#include <cuda_bf16.h>
#include <cstdint>

#define N_NODES 100000
#define IN_F    256
#define OUT_F   128
#define NEG_SLOPE 0.2f

// Scratch for support = LeakyReLU(features @ W^T): 100000 x 128 fp32 = 51.2 MB
__device__ float g_support[(size_t)N_NODES * OUT_F];

// ---------------------------------------------------------------------------
// Kernel 1: zero the output (poisoned to 0xAA by harness)
// ---------------------------------------------------------------------------
__global__ void zero_out_kernel(float4* __restrict__ out, int n4) {
    int i = blockIdx.x * blockDim.x + threadIdx.x;
    if (i < n4) out[i] = make_float4(0.f, 0.f, 0.f, 0.f);
}

// ---------------------------------------------------------------------------
// mma.sync helpers (portable tensor-core path, works on compute_103)
// ---------------------------------------------------------------------------
__device__ __forceinline__ uint32_t smem_u32(const void* p) {
    return (uint32_t)__cvta_generic_to_shared(p);
}

__device__ __forceinline__ void ldm_x4(uint32_t& r0, uint32_t& r1,
                                       uint32_t& r2, uint32_t& r3, uint32_t addr) {
    asm volatile("ldmatrix.sync.aligned.m8n8.x4.shared.b16 {%0,%1,%2,%3}, [%4];"
                 : "=r"(r0), "=r"(r1), "=r"(r2), "=r"(r3) : "r"(addr));
}

__device__ __forceinline__ void mma_bf16(float* c, const uint32_t* a,
                                         uint32_t b0, uint32_t b1) {
    asm volatile(
        "mma.sync.aligned.m16n8k16.row.col.f32.bf16.bf16.f32 "
        "{%0,%1,%2,%3}, {%4,%5,%6,%7}, {%8,%9}, {%0,%1,%2,%3};"
        : "+f"(c[0]), "+f"(c[1]), "+f"(c[2]), "+f"(c[3])
        : "r"(a[0]), "r"(a[1]), "r"(a[2]), "r"(a[3]), "r"(b0), "r"(b1));
}

__device__ __forceinline__ void sts128(uint32_t addr, const uint32_t* v) {
    asm volatile("st.shared.v4.b32 [%0], {%1, %2, %3, %4};"
                 :: "r"(addr), "r"(v[0]), "r"(v[1]), "r"(v[2]), "r"(v[3]));
}

// Split two fp32 into packed bf16x2 hi and lo (x ~= hi + lo)
__device__ __forceinline__ void split2(float a, float b, uint32_t& hi, uint32_t& lo) {
    __nv_bfloat16 ah = __float2bfloat16(a);
    __nv_bfloat16 bh = __float2bfloat16(b);
    __nv_bfloat16 al = __float2bfloat16(a - __bfloat162float(ah));
    __nv_bfloat16 bl = __float2bfloat16(b - __bfloat162float(bh));
    __nv_bfloat162 hp(ah, bh);
    __nv_bfloat162 lp(al, bl);
    hi = *reinterpret_cast<uint32_t*>(&hp);
    lo = *reinterpret_cast<uint32_t*>(&lp);
}

__device__ __forceinline__ void split8(const float4& v0, const float4& v1,
                                       uint32_t hi[4], uint32_t lo[4]) {
    split2(v0.x, v0.y, hi[0], lo[0]);
    split2(v0.z, v0.w, hi[1], lo[1]);
    split2(v1.x, v1.y, hi[2], lo[2]);
    split2(v1.z, v1.w, hi[3], lo[3]);
}

__device__ __forceinline__ float lrelu(float x) {
    return x > 0.f ? x : NEG_SLOPE * x;
}

// ---------------------------------------------------------------------------
// Kernel 2: tensor-core GEMM (bf16x3 split, mma.sync) + LeakyReLU -> g_support
//   CTA: 256 threads (8 warps, 4x2), tile M=128 N=128, K-chunks of 32
// ---------------------------------------------------------------------------
#define KC 32
#define SA_STRIDE 40   // bf16 elements per row (32 data + 8 pad) -> conflict-free ldmatrix

__global__ void __launch_bounds__(256, 2)
gemm_mma_kernel(const float* __restrict__ A,    // [N_NODES, 256]
                const float* __restrict__ W,    // [128, 256]
                float* __restrict__ S)          // [N_NODES, 128]
{
    __shared__ __nv_bfloat16 sAh[128 * SA_STRIDE];
    __shared__ __nv_bfloat16 sAl[128 * SA_STRIDE];
    __shared__ __nv_bfloat16 sBh[128 * SA_STRIDE];
    __shared__ __nv_bfloat16 sBl[128 * SA_STRIDE];

    const int tid  = threadIdx.x;
    const int wid  = tid >> 5;
    const int lane = tid & 31;
    const int rowBase = blockIdx.x * 128;

    const int warpM = (wid & 3) * 32;   // 0,32,64,96
    const int warpN = (wid >> 2) * 64;  // 0,64

    const uint32_t sAh_b = smem_u32(sAh);
    const uint32_t sAl_b = smem_u32(sAl);
    const uint32_t sBh_b = smem_u32(sBh);
    const uint32_t sBl_b = smem_u32(sBl);

    // ldmatrix per-lane offsets
    const int a_row = lane & 15;            // row within 16-row subtile
    const int a_col = (lane >> 4) * 8;      // k offset 0 or 8
    const int b_n   = (lane >> 4) * 8 + (lane & 7);   // n within 16-wide pair
    const int b_k   = ((lane >> 3) & 1) * 8;          // k offset 0 or 8

    float acc[2][8][4];
    #pragma unroll
    for (int i = 0; i < 2; i++)
        #pragma unroll
        for (int j = 0; j < 8; j++)
            #pragma unroll
            for (int q = 0; q < 4; q++) acc[i][j][q] = 0.f;

    // loader mapping: 512 items of 8 floats each per chunk, 2 per thread
    const int ldr = tid >> 1;        // handled via item index below

    for (int c = 0; c < IN_F / KC; ++c) {
        // ---- load + split A chunk [128 x 32] ----
        #pragma unroll
        for (int it = 0; it < 2; ++it) {
            int item = it * 256 + tid;   // 0..511
            int r  = item >> 2;          // 0..127
            int kg = item & 3;           // 8-float group
            int grow = rowBase + r;
            float4 v0 = make_float4(0.f, 0.f, 0.f, 0.f);
            float4 v1 = v0;
            if (grow < N_NODES) {
                const float* src = A + (size_t)grow * IN_F + c * KC + kg * 8;
                v0 = *(const float4*)src;
                v1 = *(const float4*)(src + 4);
            }
            uint32_t hi[4], lo[4];
            split8(v0, v1, hi, lo);
            uint32_t off = (uint32_t)(r * SA_STRIDE + kg * 8) * 2;
            sts128(sAh_b + off, hi);
            sts128(sAl_b + off, lo);
        }
        // ---- load + split B chunk [128 x 32] (W rows) ----
        #pragma unroll
        for (int it = 0; it < 2; ++it) {
            int item = it * 256 + tid;
            int o  = item >> 2;          // 0..127
            int kg = item & 3;
            const float* src = W + (size_t)o * IN_F + c * KC + kg * 8;
            float4 v0 = *(const float4*)src;
            float4 v1 = *(const float4*)(src + 4);
            uint32_t hi[4], lo[4];
            split8(v0, v1, hi, lo);
            uint32_t off = (uint32_t)(o * SA_STRIDE + kg * 8) * 2;
            sts128(sBh_b + off, hi);
            sts128(sBl_b + off, lo);
        }
        __syncthreads();

        // ---- compute: 2 k-steps of 16 ----
        #pragma unroll
        for (int ks = 0; ks < 2; ++ks) {
            uint32_t ah[2][4], al[2][4];
            #pragma unroll
            for (int ms = 0; ms < 2; ++ms) {
                uint32_t off = (uint32_t)((warpM + ms * 16 + a_row) * SA_STRIDE
                                          + ks * 16 + a_col) * 2;
                ldm_x4(ah[ms][0], ah[ms][1], ah[ms][2], ah[ms][3], sAh_b + off);
                ldm_x4(al[ms][0], al[ms][1], al[ms][2], al[ms][3], sAl_b + off);
            }
            #pragma unroll
            for (int np = 0; np < 4; ++np) {
                uint32_t bh[4], bl[4];
                uint32_t off = (uint32_t)((warpN + np * 16 + b_n) * SA_STRIDE
                                          + ks * 16 + b_k) * 2;
                ldm_x4(bh[0], bh[1], bh[2], bh[3], sBh_b + off);
                ldm_x4(bl[0], bl[1], bl[2], bl[3], sBl_b + off);
                #pragma unroll
                for (int ms = 0; ms < 2; ++ms) {
                    #pragma unroll
                    for (int nn = 0; nn < 2; ++nn) {
                        float* cc = acc[ms][np * 2 + nn];
                        mma_bf16(cc, ah[ms], bh[2 * nn], bh[2 * nn + 1]);
                        mma_bf16(cc, ah[ms], bl[2 * nn], bl[2 * nn + 1]);
                        mma_bf16(cc, al[ms], bh[2 * nn], bh[2 * nn + 1]);
                    }
                }
            }
        }
        __syncthreads();
    }

    // ---- epilogue: LeakyReLU + store ----
    const int gid = lane >> 2;      // 0..7
    const int tig = lane & 3;       // 0..3
    #pragma unroll
    for (int ms = 0; ms < 2; ++ms) {
        int r0 = rowBase + warpM + ms * 16 + gid;
        int r1 = r0 + 8;
        #pragma unroll
        for (int ns = 0; ns < 8; ++ns) {
            int col = warpN + ns * 8 + tig * 2;
            if (r0 < N_NODES) {
                float2 v;
                v.x = lrelu(acc[ms][ns][0]);
                v.y = lrelu(acc[ms][ns][1]);
                *(float2*)(S + (size_t)r0 * OUT_F + col) = v;
            }
            if (r1 < N_NODES) {
                float2 v;
                v.x = lrelu(acc[ms][ns][2]);
                v.y = lrelu(acc[ms][ns][3]);
                *(float2*)(S + (size_t)r1 * OUT_F + col) = v;
            }
        }
    }
}

// ---------------------------------------------------------------------------
// Kernel 3: SpMM scatter — warp per edge, float4 lanes, vector reduction
// ---------------------------------------------------------------------------
__global__ void __launch_bounds__(256)
spmm_kernel(const float* __restrict__ S,
            const float* __restrict__ edge_vals,
            const int*   __restrict__ edge_rows,
            const int*   __restrict__ edge_cols,
            float* __restrict__ out,
            int n_edges)
{
    int e    = (blockIdx.x * blockDim.x + threadIdx.x) >> 5;
    int lane = threadIdx.x & 31;
    if (e >= n_edges) return;

    int   r = edge_rows[e];
    int   c = edge_cols[e];
    float v = edge_vals[e];

    float4 g = ((const float4*)(S + (size_t)c * OUT_F))[lane];
    float4* dst = ((float4*)(out + (size_t)r * OUT_F)) + lane;

    asm volatile("red.global.add.v4.f32 [%0], {%1, %2, %3, %4};"
                 :: "l"(dst), "f"(g.x * v), "f"(g.y * v), "f"(g.z * v), "f"(g.w * v)
                 : "memory");
}

// ---------------------------------------------------------------------------
// Launch
// ---------------------------------------------------------------------------
extern "C" void kernel_launch(void* const* d_in, const int* in_sizes, int n_in,
                              void* d_out, int out_size)
{
    const float* features  = (const float*)d_in[0];
    const float* weight    = (const float*)d_in[1];
    const float* edge_vals = (const float*)d_in[2];
    const int*   edge_rows = (const int*)d_in[3];
    const int*   edge_cols = (const int*)d_in[4];
    float* out = (float*)d_out;

    const int n_edges = in_sizes[2];

    float* support;
    cudaGetSymbolAddress((void**)&support, g_support);

    // 1) zero output
    {
        int n4 = out_size / 4;
        int threads = 256;
        int blocks = (n4 + threads - 1) / threads;
        zero_out_kernel<<<blocks, threads>>>((float4*)out, n4);
    }

    // 2) tensor-core GEMM + LeakyReLU
    {
        int blocks = (N_NODES + 127) / 128;   // 782
        gemm_mma_kernel<<<blocks, 256>>>(features, weight, support);
    }

    // 3) SpMM scatter
    {
        int warps_per_block = 256 / 32;
        int blocks = (n_edges + warps_per_block - 1) / warps_per_block;
        spmm_kernel<<<blocks, 256>>>(support, edge_vals, edge_rows, edge_cols,
                                     out, n_edges);
    }
}

// round 5
// speedup vs baseline: 2.2075x; 1.7444x over previous
#include <cuda_runtime.h>
#include <cuda_bf16.h>
#include <cstdint>

#define N_NODES 100000
#define MAX_EDGES 3200000
#define IN_F    256
#define OUT_F   128
#define NEG_SLOPE 0.2f

#define NCNT 100352            // N_NODES padded to 512 multiple
#define NSCAN_BLK 196          // NCNT / 512

// ---------------------------------------------------------------------------
// Device scratch
// ---------------------------------------------------------------------------
__device__ float    g_support[(size_t)N_NODES * OUT_F];  // 51.2 MB
__device__ uint32_t g_Whi[IN_F * OUT_F / 2];             // pre-split weight hi (bf16x2)
__device__ uint32_t g_Wlo[IN_F * OUT_F / 2];             // pre-split weight lo
__device__ int      g_counts[NCNT];
__device__ int      g_scanbuf[NCNT];
__device__ int      g_partials[NSCAN_BLK];
__device__ int      g_rowptr[N_NODES + 1];
__device__ int      g_cursor[N_NODES];
__device__ int      g_ecol[MAX_EDGES];
__device__ float    g_eval[MAX_EDGES];

// ---------------------------------------------------------------------------
// Helpers
// ---------------------------------------------------------------------------
__device__ __forceinline__ uint32_t smem_u32(const void* p) {
    return (uint32_t)__cvta_generic_to_shared(p);
}

__device__ __forceinline__ void ldm_x4(uint32_t& r0, uint32_t& r1,
                                       uint32_t& r2, uint32_t& r3, uint32_t addr) {
    asm volatile("ldmatrix.sync.aligned.m8n8.x4.shared.b16 {%0,%1,%2,%3}, [%4];"
                 : "=r"(r0), "=r"(r1), "=r"(r2), "=r"(r3) : "r"(addr));
}

__device__ __forceinline__ void mma_bf16(float* c, const uint32_t* a,
                                         uint32_t b0, uint32_t b1) {
    asm volatile(
        "mma.sync.aligned.m16n8k16.row.col.f32.bf16.bf16.f32 "
        "{%0,%1,%2,%3}, {%4,%5,%6,%7}, {%8,%9}, {%0,%1,%2,%3};"
        : "+f"(c[0]), "+f"(c[1]), "+f"(c[2]), "+f"(c[3])
        : "r"(a[0]), "r"(a[1]), "r"(a[2]), "r"(a[3]), "r"(b0), "r"(b1));
}

__device__ __forceinline__ void sts128(uint32_t addr, const uint32_t* v) {
    asm volatile("st.shared.v4.b32 [%0], {%1, %2, %3, %4};"
                 :: "r"(addr), "r"(v[0]), "r"(v[1]), "r"(v[2]), "r"(v[3]));
}

// Fast split of two fp32 into packed bf16x2 hi (truncated) and lo (residual).
// hi pack: low half = high16(a), high half = high16(b)  (6 instrs / 2 elems)
__device__ __forceinline__ void split2_fast(float a, float b, uint32_t& hi, uint32_t& lo) {
    uint32_t ia = __float_as_uint(a);
    uint32_t ib = __float_as_uint(b);
    hi = __byte_perm(ia, ib, 0x7632);
    float la = a - __uint_as_float(ia & 0xFFFF0000u);
    float lb = b - __uint_as_float(ib & 0xFFFF0000u);
    asm("cvt.rn.bf16x2.f32 %0, %1, %2;" : "=r"(lo) : "f"(lb), "f"(la));
}

__device__ __forceinline__ void split8(const float4& v0, const float4& v1,
                                       uint32_t hi[4], uint32_t lo[4]) {
    split2_fast(v0.x, v0.y, hi[0], lo[0]);
    split2_fast(v0.z, v0.w, hi[1], lo[1]);
    split2_fast(v1.x, v1.y, hi[2], lo[2]);
    split2_fast(v1.z, v1.w, hi[3], lo[3]);
}

__device__ __forceinline__ float lrelu(float x) {
    return x > 0.f ? x : NEG_SLOPE * x;
}

// ---------------------------------------------------------------------------
// K: pre-split W into bf16 hi/lo (once per launch; tiny)
// ---------------------------------------------------------------------------
__global__ void split_w_kernel(const float* __restrict__ W) {
    int i = blockIdx.x * blockDim.x + threadIdx.x;   // pair index
    if (i >= IN_F * OUT_F / 2) return;
    float2 v = *(const float2*)(W + (size_t)i * 2);
    uint32_t hi, lo;
    split2_fast(v.x, v.y, hi, lo);
    g_Whi[i] = hi;
    g_Wlo[i] = lo;
}

// ---------------------------------------------------------------------------
// CSR build kernels
// ---------------------------------------------------------------------------
__global__ void zero_counts_kernel() {
    int i = blockIdx.x * blockDim.x + threadIdx.x;
    if (i < NCNT) g_counts[i] = 0;
}

__global__ void hist_kernel(const int* __restrict__ rows, int n_edges) {
    int e = blockIdx.x * blockDim.x + threadIdx.x;
    if (e < n_edges) atomicAdd(&g_counts[rows[e]], 1);
}

__global__ void __launch_bounds__(512)
scan1_kernel() {
    __shared__ int s[512];
    int t = threadIdx.x;
    int idx = blockIdx.x * 512 + t;
    int x = g_counts[idx];
    s[t] = x;
    __syncthreads();
    #pragma unroll
    for (int off = 1; off < 512; off <<= 1) {
        int v = (t >= off) ? s[t - off] : 0;
        __syncthreads();
        s[t] += v;
        __syncthreads();
    }
    g_scanbuf[idx] = s[t] - x;               // exclusive
    if (t == 511) g_partials[blockIdx.x] = s[511];
}

__global__ void scan2_kernel() {
    __shared__ int s[NSCAN_BLK];
    int t = threadIdx.x;
    if (t < NSCAN_BLK) s[t] = g_partials[t];
    __syncthreads();
    if (t == 0) {
        int run = 0;
        for (int b = 0; b < NSCAN_BLK; ++b) {
            int v = s[b];
            s[b] = run;
            run += v;
        }
    }
    __syncthreads();
    if (t < NSCAN_BLK) g_partials[t] = s[t];
}

__global__ void scan3_kernel() {
    int i = blockIdx.x * blockDim.x + threadIdx.x;
    if (i > N_NODES) return;
    int v = g_scanbuf[i] + g_partials[i >> 9];
    g_rowptr[i] = v;
    if (i < N_NODES) g_cursor[i] = v;
}

__global__ void fill_kernel(const int* __restrict__ rows,
                            const int* __restrict__ cols,
                            const float* __restrict__ vals, int n_edges) {
    int e = blockIdx.x * blockDim.x + threadIdx.x;
    if (e >= n_edges) return;
    int r = rows[e];
    int p = atomicAdd(&g_cursor[r], 1);
    g_ecol[p] = cols[e];
    g_eval[p] = vals[e];
}

// ---------------------------------------------------------------------------
// GEMM: bf16x3 split via mma.sync + LeakyReLU -> g_support
// ---------------------------------------------------------------------------
#define KC 32
#define SA_STRIDE 40   // bf16 per row (32 data + 8 pad) -> conflict-free ldmatrix

__global__ void __launch_bounds__(256, 2)
gemm_mma_kernel(const float* __restrict__ A,    // [N_NODES, 256]
                float* __restrict__ S)          // [N_NODES, 128]
{
    __shared__ __nv_bfloat16 sAh[128 * SA_STRIDE];
    __shared__ __nv_bfloat16 sAl[128 * SA_STRIDE];
    __shared__ __nv_bfloat16 sBh[128 * SA_STRIDE];
    __shared__ __nv_bfloat16 sBl[128 * SA_STRIDE];

    const int tid  = threadIdx.x;
    const int wid  = tid >> 5;
    const int lane = tid & 31;
    const int rowBase = blockIdx.x * 128;

    const int warpM = (wid & 3) * 32;   // 0,32,64,96
    const int warpN = (wid >> 2) * 64;  // 0,64

    const uint32_t sAh_b = smem_u32(sAh);
    const uint32_t sAl_b = smem_u32(sAl);
    const uint32_t sBh_b = smem_u32(sBh);
    const uint32_t sBl_b = smem_u32(sBl);

    const int a_row = lane & 15;
    const int a_col = (lane >> 4) * 8;
    const int b_n   = (lane >> 4) * 8 + (lane & 7);
    const int b_k   = ((lane >> 3) & 1) * 8;

    float acc[2][8][4];
    #pragma unroll
    for (int i = 0; i < 2; i++)
        #pragma unroll
        for (int j = 0; j < 8; j++)
            #pragma unroll
            for (int q = 0; q < 4; q++) acc[i][j][q] = 0.f;

    for (int c = 0; c < IN_F / KC; ++c) {
        // ---- load + split A chunk [128 x 32] ----
        #pragma unroll
        for (int it = 0; it < 2; ++it) {
            int item = it * 256 + tid;   // 0..511
            int r  = item >> 2;          // 0..127
            int kg = item & 3;           // 8-float group
            int grow = rowBase + r;
            float4 v0 = make_float4(0.f, 0.f, 0.f, 0.f);
            float4 v1 = v0;
            if (grow < N_NODES) {
                const float* src = A + (size_t)grow * IN_F + c * KC + kg * 8;
                v0 = *(const float4*)src;
                v1 = *(const float4*)(src + 4);
            }
            uint32_t hi[4], lo[4];
            split8(v0, v1, hi, lo);
            uint32_t off = (uint32_t)(r * SA_STRIDE + kg * 8) * 2;
            sts128(sAh_b + off, hi);
            sts128(sAl_b + off, lo);
        }
        // ---- load pre-split B chunk [128 x 32] ----
        #pragma unroll
        for (int it = 0; it < 2; ++it) {
            int item = it * 256 + tid;
            int o  = item >> 2;          // 0..127
            int kg = item & 3;
            int u32i = o * (IN_F / 2) + c * (KC / 2) + kg * 4;
            uint4 hi = *(const uint4*)(g_Whi + u32i);
            uint4 lo = *(const uint4*)(g_Wlo + u32i);
            uint32_t off = (uint32_t)(o * SA_STRIDE + kg * 8) * 2;
            sts128(sBh_b + off, (const uint32_t*)&hi);
            sts128(sBl_b + off, (const uint32_t*)&lo);
        }
        __syncthreads();

        // ---- compute: 2 k-steps of 16 ----
        #pragma unroll
        for (int ks = 0; ks < 2; ++ks) {
            uint32_t ah[2][4], al[2][4];
            #pragma unroll
            for (int ms = 0; ms < 2; ++ms) {
                uint32_t off = (uint32_t)((warpM + ms * 16 + a_row) * SA_STRIDE
                                          + ks * 16 + a_col) * 2;
                ldm_x4(ah[ms][0], ah[ms][1], ah[ms][2], ah[ms][3], sAh_b + off);
                ldm_x4(al[ms][0], al[ms][1], al[ms][2], al[ms][3], sAl_b + off);
            }
            #pragma unroll
            for (int np = 0; np < 4; ++np) {
                uint32_t bh[4], bl[4];
                uint32_t off = (uint32_t)((warpN + np * 16 + b_n) * SA_STRIDE
                                          + ks * 16 + b_k) * 2;
                ldm_x4(bh[0], bh[1], bh[2], bh[3], sBh_b + off);
                ldm_x4(bl[0], bl[1], bl[2], bl[3], sBl_b + off);
                #pragma unroll
                for (int ms = 0; ms < 2; ++ms) {
                    #pragma unroll
                    for (int nn = 0; nn < 2; ++nn) {
                        float* cc = acc[ms][np * 2 + nn];
                        mma_bf16(cc, ah[ms], bh[2 * nn], bh[2 * nn + 1]);
                        mma_bf16(cc, ah[ms], bl[2 * nn], bl[2 * nn + 1]);
                        mma_bf16(cc, al[ms], bh[2 * nn], bh[2 * nn + 1]);
                    }
                }
            }
        }
        __syncthreads();
    }

    // ---- epilogue: LeakyReLU + store ----
    const int gid = lane >> 2;
    const int tig = lane & 3;
    #pragma unroll
    for (int ms = 0; ms < 2; ++ms) {
        int r0 = rowBase + warpM + ms * 16 + gid;
        int r1 = r0 + 8;
        #pragma unroll
        for (int ns = 0; ns < 8; ++ns) {
            int col = warpN + ns * 8 + tig * 2;
            if (r0 < N_NODES) {
                float2 v;
                v.x = lrelu(acc[ms][ns][0]);
                v.y = lrelu(acc[ms][ns][1]);
                *(float2*)(S + (size_t)r0 * OUT_F + col) = v;
            }
            if (r1 < N_NODES) {
                float2 v;
                v.x = lrelu(acc[ms][ns][2]);
                v.y = lrelu(acc[ms][ns][3]);
                *(float2*)(S + (size_t)r1 * OUT_F + col) = v;
            }
        }
    }
}

// ---------------------------------------------------------------------------
// Gather: warp per row, register accumulation, no output atomics
// ---------------------------------------------------------------------------
__global__ void __launch_bounds__(256)
gather_kernel(const float* __restrict__ S, float* __restrict__ out)
{
    int row  = (blockIdx.x * blockDim.x + threadIdx.x) >> 5;
    int lane = threadIdx.x & 31;
    if (row >= N_NODES) return;

    int start = g_rowptr[row];
    int end   = g_rowptr[row + 1];

    float4 acc = make_float4(0.f, 0.f, 0.f, 0.f);

    for (int e0 = start; e0 < end; e0 += 32) {
        int n = min(32, end - e0);
        int   col = 0;
        float val = 0.f;
        if (lane < n) {
            col = g_ecol[e0 + lane];
            val = g_eval[e0 + lane];
        }
        #pragma unroll 4
        for (int j = 0; j < n; ++j) {
            int   cj = __shfl_sync(0xFFFFFFFFu, col, j);
            float vj = __shfl_sync(0xFFFFFFFFu, val, j);
            float4 g = __ldg(((const float4*)(S + (size_t)cj * OUT_F)) + lane);
            acc.x = fmaf(vj, g.x, acc.x);
            acc.y = fmaf(vj, g.y, acc.y);
            acc.z = fmaf(vj, g.z, acc.z);
            acc.w = fmaf(vj, g.w, acc.w);
        }
    }

    ((float4*)(out + (size_t)row * OUT_F))[lane] = acc;
}

// ---------------------------------------------------------------------------
// Launch
// ---------------------------------------------------------------------------
extern "C" void kernel_launch(void* const* d_in, const int* in_sizes, int n_in,
                              void* d_out, int out_size)
{
    const float* features  = (const float*)d_in[0];
    const float* weight    = (const float*)d_in[1];
    const float* edge_vals = (const float*)d_in[2];
    const int*   edge_rows = (const int*)d_in[3];
    const int*   edge_cols = (const int*)d_in[4];
    float* out = (float*)d_out;

    const int n_edges = in_sizes[2];

    float* support;
    cudaGetSymbolAddress((void**)&support, g_support);

    // W split (tiny)
    split_w_kernel<<<(IN_F * OUT_F / 2 + 255) / 256, 256>>>(weight);

    // CSR build
    zero_counts_kernel<<<(NCNT + 255) / 256, 256>>>();
    hist_kernel<<<(n_edges + 255) / 256, 256>>>(edge_rows, n_edges);
    scan1_kernel<<<NSCAN_BLK, 512>>>();
    scan2_kernel<<<1, 256>>>();
    scan3_kernel<<<(N_NODES + 1 + 255) / 256, 256>>>();
    fill_kernel<<<(n_edges + 255) / 256, 256>>>(edge_rows, edge_cols, edge_vals, n_edges);

    // GEMM + LeakyReLU
    gemm_mma_kernel<<<(N_NODES + 127) / 128, 256>>>(features, support);

    // Row-parallel gather (writes every output element; no zero pass needed)
    gather_kernel<<<(N_NODES * 32 + 255) / 256, 256>>>(support, out);
}

// round 6
// speedup vs baseline: 2.6468x; 1.1990x over previous
#include <cuda_runtime.h>
#include <cuda_bf16.h>
#include <cuda_fp16.h>
#include <cstdint>

#define N_NODES 100000
#define MAX_EDGES 3200000
#define IN_F    256
#define OUT_F   128
#define NEG_SLOPE 0.2f

#define NCNT 100352            // N_NODES padded to 512 multiple
#define NSCAN_BLK 196          // NCNT / 512

// ---------------------------------------------------------------------------
// Device scratch
// ---------------------------------------------------------------------------
__device__ __half   g_support[(size_t)N_NODES * OUT_F];  // 25.6 MB (fp16)
__device__ uint32_t g_Whi[IN_F * OUT_F / 2];             // pre-split weight hi (bf16x2)
__device__ uint32_t g_Wlo[IN_F * OUT_F / 2];             // pre-split weight lo
__device__ int      g_counts[NCNT];
__device__ int      g_scanbuf[NCNT];
__device__ int      g_partials[NSCAN_BLK];
__device__ int      g_rowptr[N_NODES + 1];
__device__ int      g_cursor[N_NODES];
__device__ int2     g_epack[MAX_EDGES];                  // (col, val-bits)

// ---------------------------------------------------------------------------
// Helpers
// ---------------------------------------------------------------------------
__device__ __forceinline__ uint32_t smem_u32(const void* p) {
    return (uint32_t)__cvta_generic_to_shared(p);
}

__device__ __forceinline__ void ldm_x4(uint32_t& r0, uint32_t& r1,
                                       uint32_t& r2, uint32_t& r3, uint32_t addr) {
    asm volatile("ldmatrix.sync.aligned.m8n8.x4.shared.b16 {%0,%1,%2,%3}, [%4];"
                 : "=r"(r0), "=r"(r1), "=r"(r2), "=r"(r3) : "r"(addr));
}

__device__ __forceinline__ void mma_bf16(float* c, const uint32_t* a,
                                         uint32_t b0, uint32_t b1) {
    asm volatile(
        "mma.sync.aligned.m16n8k16.row.col.f32.bf16.bf16.f32 "
        "{%0,%1,%2,%3}, {%4,%5,%6,%7}, {%8,%9}, {%0,%1,%2,%3};"
        : "+f"(c[0]), "+f"(c[1]), "+f"(c[2]), "+f"(c[3])
        : "r"(a[0]), "r"(a[1]), "r"(a[2]), "r"(a[3]), "r"(b0), "r"(b1));
}

__device__ __forceinline__ void sts128(uint32_t addr, const uint32_t* v) {
    asm volatile("st.shared.v4.b32 [%0], {%1, %2, %3, %4};"
                 :: "r"(addr), "r"(v[0]), "r"(v[1]), "r"(v[2]), "r"(v[3]));
}

// Fast split of two fp32 into packed bf16x2 hi (truncated) and lo (residual).
__device__ __forceinline__ void split2_fast(float a, float b, uint32_t& hi, uint32_t& lo) {
    uint32_t ia = __float_as_uint(a);
    uint32_t ib = __float_as_uint(b);
    hi = __byte_perm(ia, ib, 0x7632);
    float la = a - __uint_as_float(ia & 0xFFFF0000u);
    float lb = b - __uint_as_float(ib & 0xFFFF0000u);
    asm("cvt.rn.bf16x2.f32 %0, %1, %2;" : "=r"(lo) : "f"(lb), "f"(la));
}

__device__ __forceinline__ void split8(const float4& v0, const float4& v1,
                                       uint32_t hi[4], uint32_t lo[4]) {
    split2_fast(v0.x, v0.y, hi[0], lo[0]);
    split2_fast(v0.z, v0.w, hi[1], lo[1]);
    split2_fast(v1.x, v1.y, hi[2], lo[2]);
    split2_fast(v1.z, v1.w, hi[3], lo[3]);
}

__device__ __forceinline__ float lrelu(float x) {
    return x > 0.f ? x : NEG_SLOPE * x;
}

// ---------------------------------------------------------------------------
// W pre-split (tiny)
// ---------------------------------------------------------------------------
__global__ void split_w_kernel(const float* __restrict__ W) {
    int i = blockIdx.x * blockDim.x + threadIdx.x;
    if (i >= IN_F * OUT_F / 2) return;
    float2 v = *(const float2*)(W + (size_t)i * 2);
    uint32_t hi, lo;
    split2_fast(v.x, v.y, hi, lo);
    g_Whi[i] = hi;
    g_Wlo[i] = lo;
}

// ---------------------------------------------------------------------------
// CSR build kernels
// ---------------------------------------------------------------------------
__global__ void zero_counts_kernel() {
    int i = blockIdx.x * blockDim.x + threadIdx.x;
    if (i < NCNT) g_counts[i] = 0;
}

__global__ void hist_kernel(const int* __restrict__ rows, int n_edges) {
    int e = blockIdx.x * blockDim.x + threadIdx.x;
    if (e < n_edges) atomicAdd(&g_counts[rows[e]], 1);
}

__global__ void __launch_bounds__(512)
scan1_kernel() {
    __shared__ int s[512];
    int t = threadIdx.x;
    int idx = blockIdx.x * 512 + t;
    int x = g_counts[idx];
    s[t] = x;
    __syncthreads();
    #pragma unroll
    for (int off = 1; off < 512; off <<= 1) {
        int v = (t >= off) ? s[t - off] : 0;
        __syncthreads();
        s[t] += v;
        __syncthreads();
    }
    g_scanbuf[idx] = s[t] - x;               // exclusive
    if (t == 511) g_partials[blockIdx.x] = s[511];
}

__global__ void scan2_kernel() {
    __shared__ int s[NSCAN_BLK];
    int t = threadIdx.x;
    if (t < NSCAN_BLK) s[t] = g_partials[t];
    __syncthreads();
    if (t == 0) {
        int run = 0;
        for (int b = 0; b < NSCAN_BLK; ++b) {
            int v = s[b];
            s[b] = run;
            run += v;
        }
    }
    __syncthreads();
    if (t < NSCAN_BLK) g_partials[t] = s[t];
}

__global__ void scan3_kernel() {
    int i = blockIdx.x * blockDim.x + threadIdx.x;
    if (i > N_NODES) return;
    int v = g_scanbuf[i] + g_partials[i >> 9];
    g_rowptr[i] = v;
    if (i < N_NODES) g_cursor[i] = v;
}

__global__ void fill_kernel(const int* __restrict__ rows,
                            const int* __restrict__ cols,
                            const float* __restrict__ vals, int n_edges) {
    int e = blockIdx.x * blockDim.x + threadIdx.x;
    if (e >= n_edges) return;
    int r = rows[e];
    int p = atomicAdd(&g_cursor[r], 1);
    g_epack[p] = make_int2(cols[e], __float_as_int(vals[e]));
}

// ---------------------------------------------------------------------------
// GEMM: bf16x3 split via mma.sync + LeakyReLU -> g_support (fp16)
// ---------------------------------------------------------------------------
#define KC 32
#define SA_STRIDE 40   // bf16 per row (32 data + 8 pad) -> conflict-free ldmatrix

__global__ void __launch_bounds__(256, 2)
gemm_mma_kernel(const float* __restrict__ A,    // [N_NODES, 256]
                __half* __restrict__ S)         // [N_NODES, 128] fp16
{
    __shared__ __nv_bfloat16 sAh[128 * SA_STRIDE];
    __shared__ __nv_bfloat16 sAl[128 * SA_STRIDE];
    __shared__ __nv_bfloat16 sBh[128 * SA_STRIDE];
    __shared__ __nv_bfloat16 sBl[128 * SA_STRIDE];

    const int tid  = threadIdx.x;
    const int wid  = tid >> 5;
    const int lane = tid & 31;
    const int rowBase = blockIdx.x * 128;

    const int warpM = (wid & 3) * 32;   // 0,32,64,96
    const int warpN = (wid >> 2) * 64;  // 0,64

    const uint32_t sAh_b = smem_u32(sAh);
    const uint32_t sAl_b = smem_u32(sAl);
    const uint32_t sBh_b = smem_u32(sBh);
    const uint32_t sBl_b = smem_u32(sBl);

    const int a_row = lane & 15;
    const int a_col = (lane >> 4) * 8;
    const int b_n   = (lane >> 4) * 8 + (lane & 7);
    const int b_k   = ((lane >> 3) & 1) * 8;

    float acc[2][8][4];
    #pragma unroll
    for (int i = 0; i < 2; i++)
        #pragma unroll
        for (int j = 0; j < 8; j++)
            #pragma unroll
            for (int q = 0; q < 4; q++) acc[i][j][q] = 0.f;

    for (int c = 0; c < IN_F / KC; ++c) {
        // ---- load + split A chunk [128 x 32] ----
        #pragma unroll
        for (int it = 0; it < 2; ++it) {
            int item = it * 256 + tid;   // 0..511
            int r  = item >> 2;          // 0..127
            int kg = item & 3;           // 8-float group
            int grow = rowBase + r;
            float4 v0 = make_float4(0.f, 0.f, 0.f, 0.f);
            float4 v1 = v0;
            if (grow < N_NODES) {
                const float* src = A + (size_t)grow * IN_F + c * KC + kg * 8;
                v0 = *(const float4*)src;
                v1 = *(const float4*)(src + 4);
            }
            uint32_t hi[4], lo[4];
            split8(v0, v1, hi, lo);
            uint32_t off = (uint32_t)(r * SA_STRIDE + kg * 8) * 2;
            sts128(sAh_b + off, hi);
            sts128(sAl_b + off, lo);
        }
        // ---- load pre-split B chunk [128 x 32] ----
        #pragma unroll
        for (int it = 0; it < 2; ++it) {
            int item = it * 256 + tid;
            int o  = item >> 2;          // 0..127
            int kg = item & 3;
            int u32i = o * (IN_F / 2) + c * (KC / 2) + kg * 4;
            uint4 hi = *(const uint4*)(g_Whi + u32i);
            uint4 lo = *(const uint4*)(g_Wlo + u32i);
            uint32_t off = (uint32_t)(o * SA_STRIDE + kg * 8) * 2;
            sts128(sBh_b + off, (const uint32_t*)&hi);
            sts128(sBl_b + off, (const uint32_t*)&lo);
        }
        __syncthreads();

        // ---- compute: 2 k-steps of 16 ----
        #pragma unroll
        for (int ks = 0; ks < 2; ++ks) {
            uint32_t ah[2][4], al[2][4];
            #pragma unroll
            for (int ms = 0; ms < 2; ++ms) {
                uint32_t off = (uint32_t)((warpM + ms * 16 + a_row) * SA_STRIDE
                                          + ks * 16 + a_col) * 2;
                ldm_x4(ah[ms][0], ah[ms][1], ah[ms][2], ah[ms][3], sAh_b + off);
                ldm_x4(al[ms][0], al[ms][1], al[ms][2], al[ms][3], sAl_b + off);
            }
            #pragma unroll
            for (int np = 0; np < 4; ++np) {
                uint32_t bh[4], bl[4];
                uint32_t off = (uint32_t)((warpN + np * 16 + b_n) * SA_STRIDE
                                          + ks * 16 + b_k) * 2;
                ldm_x4(bh[0], bh[1], bh[2], bh[3], sBh_b + off);
                ldm_x4(bl[0], bl[1], bl[2], bl[3], sBl_b + off);
                #pragma unroll
                for (int ms = 0; ms < 2; ++ms) {
                    #pragma unroll
                    for (int nn = 0; nn < 2; ++nn) {
                        float* cc = acc[ms][np * 2 + nn];
                        mma_bf16(cc, ah[ms], bh[2 * nn], bh[2 * nn + 1]);
                        mma_bf16(cc, ah[ms], bl[2 * nn], bl[2 * nn + 1]);
                        mma_bf16(cc, al[ms], bh[2 * nn], bh[2 * nn + 1]);
                    }
                }
            }
        }
        __syncthreads();
    }

    // ---- epilogue: LeakyReLU + fp16 store ----
    const int gid = lane >> 2;
    const int tig = lane & 3;
    #pragma unroll
    for (int ms = 0; ms < 2; ++ms) {
        int r0 = rowBase + warpM + ms * 16 + gid;
        int r1 = r0 + 8;
        #pragma unroll
        for (int ns = 0; ns < 8; ++ns) {
            int col = warpN + ns * 8 + tig * 2;
            if (r0 < N_NODES) {
                __half2 h = __float22half2_rn(
                    make_float2(lrelu(acc[ms][ns][0]), lrelu(acc[ms][ns][1])));
                *(__half2*)(S + (size_t)r0 * OUT_F + col) = h;
            }
            if (r1 < N_NODES) {
                __half2 h = __float22half2_rn(
                    make_float2(lrelu(acc[ms][ns][2]), lrelu(acc[ms][ns][3])));
                *(__half2*)(S + (size_t)r1 * OUT_F + col) = h;
            }
        }
    }
}

// ---------------------------------------------------------------------------
// Gather: warp per row, fp16 support, fp32 register accumulation
// ---------------------------------------------------------------------------
__global__ void __launch_bounds__(256)
gather_kernel(const __half* __restrict__ S, float* __restrict__ out)
{
    int row  = (blockIdx.x * blockDim.x + threadIdx.x) >> 5;
    int lane = threadIdx.x & 31;
    if (row >= N_NODES) return;

    int start = g_rowptr[row];
    int end   = g_rowptr[row + 1];

    float4 acc = make_float4(0.f, 0.f, 0.f, 0.f);

    for (int e0 = start; e0 < end; e0 += 32) {
        int n = min(32, end - e0);
        int2 p = make_int2(0, 0);
        if (lane < n) p = g_epack[e0 + lane];

        #pragma unroll 4
        for (int j = 0; j < n; ++j) {
            int   cj = __shfl_sync(0xFFFFFFFFu, p.x, j);
            float vj = __int_as_float(__shfl_sync(0xFFFFFFFFu, p.y, j));
            // lane covers 4 fp16 columns: [lane*4, lane*4+3]
            uint2 hbits = __ldg((const uint2*)(S + (size_t)cj * OUT_F) + lane);
            __half2 h0 = *reinterpret_cast<__half2*>(&hbits.x);
            __half2 h1 = *reinterpret_cast<__half2*>(&hbits.y);
            float2 f0 = __half22float2(h0);
            float2 f1 = __half22float2(h1);
            acc.x = fmaf(vj, f0.x, acc.x);
            acc.y = fmaf(vj, f0.y, acc.y);
            acc.z = fmaf(vj, f1.x, acc.z);
            acc.w = fmaf(vj, f1.y, acc.w);
        }
    }

    *((float4*)(out + (size_t)row * OUT_F) + lane) = acc;
}

// ---------------------------------------------------------------------------
// Launch
// ---------------------------------------------------------------------------
extern "C" void kernel_launch(void* const* d_in, const int* in_sizes, int n_in,
                              void* d_out, int out_size)
{
    const float* features  = (const float*)d_in[0];
    const float* weight    = (const float*)d_in[1];
    const float* edge_vals = (const float*)d_in[2];
    const int*   edge_rows = (const int*)d_in[3];
    const int*   edge_cols = (const int*)d_in[4];
    float* out = (float*)d_out;

    const int n_edges = in_sizes[2];

    __half* support;
    cudaGetSymbolAddress((void**)&support, g_support);

    // W split (tiny)
    split_w_kernel<<<(IN_F * OUT_F / 2 + 255) / 256, 256>>>(weight);

    // CSR build
    zero_counts_kernel<<<(NCNT + 255) / 256, 256>>>();
    hist_kernel<<<(n_edges + 255) / 256, 256>>>(edge_rows, n_edges);
    scan1_kernel<<<NSCAN_BLK, 512>>>();
    scan2_kernel<<<1, 256>>>();
    scan3_kernel<<<(N_NODES + 1 + 255) / 256, 256>>>();
    fill_kernel<<<(n_edges + 255) / 256, 256>>>(edge_rows, edge_cols, edge_vals, n_edges);

    // GEMM + LeakyReLU (fp16 out)
    gemm_mma_kernel<<<(N_NODES + 127) / 128, 256>>>(features, support);

    // Row-parallel gather
    gather_kernel<<<(N_NODES * 32 + 255) / 256, 256>>>(support, out);
}

// round 7
// speedup vs baseline: 2.7503x; 1.0391x over previous
#include <cuda_runtime.h>
#include <cuda_bf16.h>
#include <cuda_fp16.h>
#include <cstdint>

#define N_NODES 100000
#define MAX_EDGES 3200000
#define IN_F    256
#define OUT_F   128
#define NEG_SLOPE 0.2f

#define NCNT 100352            // N_NODES padded to 512 multiple
#define NSCAN_BLK 196          // NCNT / 512

// ---------------------------------------------------------------------------
// Device scratch
// ---------------------------------------------------------------------------
__device__ __half   g_support[(size_t)N_NODES * OUT_F];  // 25.6 MB (fp16)
__device__ uint32_t g_Whi[IN_F * OUT_F / 2];             // pre-split weight hi (bf16x2)
__device__ uint32_t g_Wlo[IN_F * OUT_F / 2];             // pre-split weight lo
__device__ int      g_counts[NCNT];
__device__ int      g_scanbuf[NCNT];
__device__ int      g_partials[NSCAN_BLK];
__device__ int      g_rowptr[N_NODES + 1];
__device__ int      g_cursor[N_NODES];
__device__ int2     g_epack[MAX_EDGES];                  // (col, val-bits)

// ---------------------------------------------------------------------------
// Helpers
// ---------------------------------------------------------------------------
__device__ __forceinline__ uint32_t smem_u32(const void* p) {
    return (uint32_t)__cvta_generic_to_shared(p);
}

__device__ __forceinline__ void ldm_x4(uint32_t& r0, uint32_t& r1,
                                       uint32_t& r2, uint32_t& r3, uint32_t addr) {
    asm volatile("ldmatrix.sync.aligned.m8n8.x4.shared.b16 {%0,%1,%2,%3}, [%4];"
                 : "=r"(r0), "=r"(r1), "=r"(r2), "=r"(r3) : "r"(addr));
}

__device__ __forceinline__ void mma_bf16(float* c, const uint32_t* a,
                                         uint32_t b0, uint32_t b1) {
    asm volatile(
        "mma.sync.aligned.m16n8k16.row.col.f32.bf16.bf16.f32 "
        "{%0,%1,%2,%3}, {%4,%5,%6,%7}, {%8,%9}, {%0,%1,%2,%3};"
        : "+f"(c[0]), "+f"(c[1]), "+f"(c[2]), "+f"(c[3])
        : "r"(a[0]), "r"(a[1]), "r"(a[2]), "r"(a[3]), "r"(b0), "r"(b1));
}

__device__ __forceinline__ void sts128(uint32_t addr, const uint32_t* v) {
    asm volatile("st.shared.v4.b32 [%0], {%1, %2, %3, %4};"
                 :: "r"(addr), "r"(v[0]), "r"(v[1]), "r"(v[2]), "r"(v[3]));
}

// Fast split of two fp32 into packed bf16x2 hi (truncated) and lo (residual).
__device__ __forceinline__ void split2_fast(float a, float b, uint32_t& hi, uint32_t& lo) {
    uint32_t ia = __float_as_uint(a);
    uint32_t ib = __float_as_uint(b);
    hi = __byte_perm(ia, ib, 0x7632);
    float la = a - __uint_as_float(ia & 0xFFFF0000u);
    float lb = b - __uint_as_float(ib & 0xFFFF0000u);
    asm("cvt.rn.bf16x2.f32 %0, %1, %2;" : "=r"(lo) : "f"(lb), "f"(la));
}

__device__ __forceinline__ void split8(const float4& v0, const float4& v1,
                                       uint32_t hi[4], uint32_t lo[4]) {
    split2_fast(v0.x, v0.y, hi[0], lo[0]);
    split2_fast(v0.z, v0.w, hi[1], lo[1]);
    split2_fast(v1.x, v1.y, hi[2], lo[2]);
    split2_fast(v1.z, v1.w, hi[3], lo[3]);
}

__device__ __forceinline__ float lrelu(float x) {
    return x > 0.f ? x : NEG_SLOPE * x;
}

// ---------------------------------------------------------------------------
// W pre-split (tiny)
// ---------------------------------------------------------------------------
__global__ void split_w_kernel(const float* __restrict__ W) {
    int i = blockIdx.x * blockDim.x + threadIdx.x;
    if (i >= IN_F * OUT_F / 2) return;
    float2 v = *(const float2*)(W + (size_t)i * 2);
    uint32_t hi, lo;
    split2_fast(v.x, v.y, hi, lo);
    g_Whi[i] = hi;
    g_Wlo[i] = lo;
}

// ---------------------------------------------------------------------------
// CSR build kernels
// ---------------------------------------------------------------------------
__global__ void zero_counts_kernel() {
    int i = blockIdx.x * blockDim.x + threadIdx.x;
    if (i * 4 < NCNT) *(int4*)(g_counts + i * 4) = make_int4(0, 0, 0, 0);
}

__global__ void hist_kernel(const int* __restrict__ rows, int n_edges) {
    int i = blockIdx.x * blockDim.x + threadIdx.x;
    int base = i * 4;
    if (base + 3 < n_edges) {
        int4 r = *(const int4*)(rows + base);
        atomicAdd(&g_counts[r.x], 1);
        atomicAdd(&g_counts[r.y], 1);
        atomicAdd(&g_counts[r.z], 1);
        atomicAdd(&g_counts[r.w], 1);
    } else {
        for (int e = base; e < n_edges; ++e)
            atomicAdd(&g_counts[rows[e]], 1);
    }
}

__global__ void __launch_bounds__(512)
scan1_kernel() {
    __shared__ int s[512];
    int t = threadIdx.x;
    int idx = blockIdx.x * 512 + t;
    int x = g_counts[idx];
    s[t] = x;
    __syncthreads();
    #pragma unroll
    for (int off = 1; off < 512; off <<= 1) {
        int v = (t >= off) ? s[t - off] : 0;
        __syncthreads();
        s[t] += v;
        __syncthreads();
    }
    g_scanbuf[idx] = s[t] - x;               // exclusive
    if (t == 511) g_partials[blockIdx.x] = s[511];
}

__global__ void scan2_kernel() {
    __shared__ int s[NSCAN_BLK];
    int t = threadIdx.x;
    if (t < NSCAN_BLK) s[t] = g_partials[t];
    __syncthreads();
    if (t == 0) {
        int run = 0;
        for (int b = 0; b < NSCAN_BLK; ++b) {
            int v = s[b];
            s[b] = run;
            run += v;
        }
    }
    __syncthreads();
    if (t < NSCAN_BLK) g_partials[t] = s[t];
}

__global__ void scan3_kernel() {
    int i = blockIdx.x * blockDim.x + threadIdx.x;
    if (i > N_NODES) return;
    int v = g_scanbuf[i] + g_partials[i >> 9];
    g_rowptr[i] = v;
    if (i < N_NODES) g_cursor[i] = v;
}

__global__ void fill_kernel(const int* __restrict__ rows,
                            const int* __restrict__ cols,
                            const float* __restrict__ vals, int n_edges) {
    int e = blockIdx.x * blockDim.x + threadIdx.x;
    if (e >= n_edges) return;
    int r = rows[e];
    int p = atomicAdd(&g_cursor[r], 1);
    g_epack[p] = make_int2(cols[e], __float_as_int(vals[e]));
}

// ---------------------------------------------------------------------------
// GEMM: bf16x3 split via mma.sync, software-pipelined A loads, fp16 out
// ---------------------------------------------------------------------------
#define KC 32
#define NCHUNK (IN_F / KC)   // 8
#define SA_STRIDE 40   // bf16 per row (32 data + 8 pad) -> conflict-free ldmatrix

__global__ void __launch_bounds__(256, 2)
gemm_mma_kernel(const float* __restrict__ A,    // [N_NODES, 256]
                __half* __restrict__ S)         // [N_NODES, 128] fp16
{
    __shared__ __nv_bfloat16 sAh[128 * SA_STRIDE];
    __shared__ __nv_bfloat16 sAl[128 * SA_STRIDE];
    __shared__ __nv_bfloat16 sBh[128 * SA_STRIDE];
    __shared__ __nv_bfloat16 sBl[128 * SA_STRIDE];

    const int tid  = threadIdx.x;
    const int wid  = tid >> 5;
    const int lane = tid & 31;
    const int rowBase = blockIdx.x * 128;

    const int warpM = (wid & 3) * 32;   // 0,32,64,96
    const int warpN = (wid >> 2) * 64;  // 0,64

    const uint32_t sAh_b = smem_u32(sAh);
    const uint32_t sAl_b = smem_u32(sAl);
    const uint32_t sBh_b = smem_u32(sBh);
    const uint32_t sBl_b = smem_u32(sBl);

    const int a_row = lane & 15;
    const int a_col = (lane >> 4) * 8;
    const int b_n   = (lane >> 4) * 8 + (lane & 7);
    const int b_k   = ((lane >> 3) & 1) * 8;

    // Loader mapping (same for every chunk): 2 items per thread
    const int it_r0  = tid >> 2;             // item0 row  (items 0..255)
    const int it_kg0 = tid & 3;
    const int it_r1  = (256 + tid) >> 2;     // item1 row  (items 256..511)
    const int it_kg1 = tid & 3;              // (256+tid)&3 == tid&3

    const bool ok0 = (rowBase + it_r0) < N_NODES;
    const bool ok1 = (rowBase + it_r1) < N_NODES;
    const float* aptr0 = A + (size_t)(rowBase + it_r0) * IN_F + it_kg0 * 8;
    const float* aptr1 = A + (size_t)(rowBase + it_r1) * IN_F + it_kg1 * 8;

    float acc[2][8][4];
    #pragma unroll
    for (int i = 0; i < 2; i++)
        #pragma unroll
        for (int j = 0; j < 8; j++)
            #pragma unroll
            for (int q = 0; q < 4; q++) acc[i][j][q] = 0.f;

    // Prefetch chunk 0 of A
    float4 pv[4];
    pv[0] = pv[1] = pv[2] = pv[3] = make_float4(0.f, 0.f, 0.f, 0.f);
    if (ok0) { pv[0] = *(const float4*)aptr0; pv[1] = *(const float4*)(aptr0 + 4); }
    if (ok1) { pv[2] = *(const float4*)aptr1; pv[3] = *(const float4*)(aptr1 + 4); }

    #pragma unroll
    for (int c = 0; c < NCHUNK; ++c) {
        // ---- split prefetched A, store to smem ----
        {
            uint32_t hi[4], lo[4];
            split8(pv[0], pv[1], hi, lo);
            uint32_t off = (uint32_t)(it_r0 * SA_STRIDE + it_kg0 * 8) * 2;
            sts128(sAh_b + off, hi);
            sts128(sAl_b + off, lo);
            split8(pv[2], pv[3], hi, lo);
            off = (uint32_t)(it_r1 * SA_STRIDE + it_kg1 * 8) * 2;
            sts128(sAh_b + off, hi);
            sts128(sAl_b + off, lo);
        }
        // ---- load pre-split B chunk [128 x 32] ----
        #pragma unroll
        for (int it = 0; it < 2; ++it) {
            int item = it * 256 + tid;
            int o  = item >> 2;          // 0..127
            int kg = item & 3;
            int u32i = o * (IN_F / 2) + c * (KC / 2) + kg * 4;
            uint4 hi = *(const uint4*)(g_Whi + u32i);
            uint4 lo = *(const uint4*)(g_Wlo + u32i);
            uint32_t off = (uint32_t)(o * SA_STRIDE + kg * 8) * 2;
            sts128(sBh_b + off, (const uint32_t*)&hi);
            sts128(sBl_b + off, (const uint32_t*)&lo);
        }
        __syncthreads();

        // ---- prefetch A chunk c+1 (overlaps with MMAs below) ----
        if (c + 1 < NCHUNK) {
            const float* p0 = aptr0 + (c + 1) * KC;
            const float* p1 = aptr1 + (c + 1) * KC;
            if (ok0) { pv[0] = *(const float4*)p0; pv[1] = *(const float4*)(p0 + 4); }
            if (ok1) { pv[2] = *(const float4*)p1; pv[3] = *(const float4*)(p1 + 4); }
        }

        // ---- compute: 2 k-steps of 16 ----
        #pragma unroll
        for (int ks = 0; ks < 2; ++ks) {
            uint32_t ah[2][4], al[2][4];
            #pragma unroll
            for (int ms = 0; ms < 2; ++ms) {
                uint32_t off = (uint32_t)((warpM + ms * 16 + a_row) * SA_STRIDE
                                          + ks * 16 + a_col) * 2;
                ldm_x4(ah[ms][0], ah[ms][1], ah[ms][2], ah[ms][3], sAh_b + off);
                ldm_x4(al[ms][0], al[ms][1], al[ms][2], al[ms][3], sAl_b + off);
            }
            #pragma unroll
            for (int np = 0; np < 4; ++np) {
                uint32_t bh[4], bl[4];
                uint32_t off = (uint32_t)((warpN + np * 16 + b_n) * SA_STRIDE
                                          + ks * 16 + b_k) * 2;
                ldm_x4(bh[0], bh[1], bh[2], bh[3], sBh_b + off);
                ldm_x4(bl[0], bl[1], bl[2], bl[3], sBl_b + off);
                #pragma unroll
                for (int ms = 0; ms < 2; ++ms) {
                    #pragma unroll
                    for (int nn = 0; nn < 2; ++nn) {
                        float* cc = acc[ms][np * 2 + nn];
                        mma_bf16(cc, ah[ms], bh[2 * nn], bh[2 * nn + 1]);
                        mma_bf16(cc, ah[ms], bl[2 * nn], bl[2 * nn + 1]);
                        mma_bf16(cc, al[ms], bh[2 * nn], bh[2 * nn + 1]);
                    }
                }
            }
        }
        __syncthreads();
    }

    // ---- epilogue: LeakyReLU + fp16 store ----
    const int gid = lane >> 2;
    const int tig = lane & 3;
    #pragma unroll
    for (int ms = 0; ms < 2; ++ms) {
        int r0 = rowBase + warpM + ms * 16 + gid;
        int r1 = r0 + 8;
        #pragma unroll
        for (int ns = 0; ns < 8; ++ns) {
            int col = warpN + ns * 8 + tig * 2;
            if (r0 < N_NODES) {
                __half2 h = __float22half2_rn(
                    make_float2(lrelu(acc[ms][ns][0]), lrelu(acc[ms][ns][1])));
                *(__half2*)(S + (size_t)r0 * OUT_F + col) = h;
            }
            if (r1 < N_NODES) {
                __half2 h = __float22half2_rn(
                    make_float2(lrelu(acc[ms][ns][2]), lrelu(acc[ms][ns][3])));
                *(__half2*)(S + (size_t)r1 * OUT_F + col) = h;
            }
        }
    }
}

// ---------------------------------------------------------------------------
// Gather: warp per row, broadcast edge loads (no shfl), unroll-2
// ---------------------------------------------------------------------------
__device__ __forceinline__ void gacc(float4& acc, float vj, uint2 hbits) {
    __half2 h0 = *reinterpret_cast<__half2*>(&hbits.x);
    __half2 h1 = *reinterpret_cast<__half2*>(&hbits.y);
    float2 f0 = __half22float2(h0);
    float2 f1 = __half22float2(h1);
    acc.x = fmaf(vj, f0.x, acc.x);
    acc.y = fmaf(vj, f0.y, acc.y);
    acc.z = fmaf(vj, f1.x, acc.z);
    acc.w = fmaf(vj, f1.y, acc.w);
}

__global__ void __launch_bounds__(256)
gather_kernel(const __half* __restrict__ S, float* __restrict__ out)
{
    int row  = (blockIdx.x * blockDim.x + threadIdx.x) >> 5;
    int lane = threadIdx.x & 31;
    if (row >= N_NODES) return;

    int j   = g_rowptr[row];
    int end = g_rowptr[row + 1];

    float4 acc = make_float4(0.f, 0.f, 0.f, 0.f);
    const uint2* Sb = (const uint2*)S;   // 32 uint2 per row

    // Align to even index for int4 (2-edge) loads
    if (j < end && (j & 1)) {
        int2 p = g_epack[j];
        uint2 hb = __ldg(Sb + (size_t)p.x * 32 + lane);
        gacc(acc, __int_as_float(p.y), hb);
        ++j;
    }
    for (; j + 1 < end; j += 2) {
        int4 pp = *(const int4*)(g_epack + j);   // 16B aligned, warp-uniform
        uint2 hb0 = __ldg(Sb + (size_t)pp.x * 32 + lane);
        uint2 hb1 = __ldg(Sb + (size_t)pp.z * 32 + lane);
        gacc(acc, __int_as_float(pp.y), hb0);
        gacc(acc, __int_as_float(pp.w), hb1);
    }
    if (j < end) {
        int2 p = g_epack[j];
        uint2 hb = __ldg(Sb + (size_t)p.x * 32 + lane);
        gacc(acc, __int_as_float(p.y), hb);
    }

    *((float4*)(out + (size_t)row * OUT_F) + lane) = acc;
}

// ---------------------------------------------------------------------------
// Launch
// ---------------------------------------------------------------------------
extern "C" void kernel_launch(void* const* d_in, const int* in_sizes, int n_in,
                              void* d_out, int out_size)
{
    const float* features  = (const float*)d_in[0];
    const float* weight    = (const float*)d_in[1];
    const float* edge_vals = (const float*)d_in[2];
    const int*   edge_rows = (const int*)d_in[3];
    const int*   edge_cols = (const int*)d_in[4];
    float* out = (float*)d_out;

    const int n_edges = in_sizes[2];

    __half* support;
    cudaGetSymbolAddress((void**)&support, g_support);

    // W split (tiny)
    split_w_kernel<<<(IN_F * OUT_F / 2 + 255) / 256, 256>>>(weight);

    // CSR build
    zero_counts_kernel<<<(NCNT / 4 + 255) / 256, 256>>>();
    hist_kernel<<<((n_edges + 3) / 4 + 255) / 256, 256>>>(edge_rows, n_edges);
    scan1_kernel<<<NSCAN_BLK, 512>>>();
    scan2_kernel<<<1, 256>>>();
    scan3_kernel<<<(N_NODES + 1 + 255) / 256, 256>>>();
    fill_kernel<<<(n_edges + 255) / 256, 256>>>(edge_rows, edge_cols, edge_vals, n_edges);

    // GEMM + LeakyReLU (fp16 out)
    gemm_mma_kernel<<<(N_NODES + 127) / 128, 256>>>(features, support);

    // Row-parallel gather
    gather_kernel<<<(N_NODES * 32 + 255) / 256, 256>>>(support, out);
}